// round 5
// baseline (speedup 1.0000x reference)
#include <cuda_runtime.h>
#include <cuda_bf16.h>
#include <cstdint>
#include <math.h>

// LSTM B=128, S=256, I=1024, H=1024. out[b,s,h] fp32.
// Phase 1: Xp[s][b][4H] = x @ Wx^T + bias (tf32 mma, 128x128 tiles, reg-pipelined)
// Phase 2: persistent 128-CTA scan, 512 thr, 4(m)x4(k) warps,
//          WARP-PRIVATE cp.async double-buffered staging (no block syncs in loop).

#define NBLK2 128
#define WS_STRIDE 1028               // 1024 + 4 pad (u32) -> conflict-free B reads
#define ST_STRIDE 20                 // 16 cols + 4 pad (u32) -> conflict-free A reads
#define ST_WORDS_PER_BUF (32 * ST_STRIDE)           // 640 u32 per warp per buffer
#define ST_WORDS_PER_WARP (2 * ST_WORDS_PER_BUF)    // double buffered
#define SMEM2_BYTES (32*WS_STRIDE*4 + 16*ST_WORDS_PER_WARP*4)   // 131584 + 81920 = 213504

__device__ __align__(16) float    g_Xp[(size_t)256 * 128 * 4096];  // 512 MB
__device__ __align__(16) uint32_t g_h[2 * 128 * 1024];             // h as tf32 bits
__device__ unsigned g_arrive = 0;

__device__ __forceinline__ uint32_t f2tf32(float f) {
    uint32_t u;
    asm volatile("cvt.rna.tf32.f32 %0, %1;" : "=r"(u) : "f"(f));
    return u;
}

__device__ __forceinline__ void mma_tf32(float d[4], const uint32_t a[4], const uint32_t b[2]) {
    asm volatile(
        "mma.sync.aligned.m16n8k8.row.col.f32.tf32.tf32.f32 "
        "{%0,%1,%2,%3},{%4,%5,%6,%7},{%8,%9},{%0,%1,%2,%3};"
        : "+f"(d[0]), "+f"(d[1]), "+f"(d[2]), "+f"(d[3])
        : "r"(a[0]), "r"(a[1]), "r"(a[2]), "r"(a[3]), "r"(b[0]), "r"(b[1]));
}

__device__ __forceinline__ float sigm(float x) { return 1.0f / (1.0f + expf(-x)); }

// ---------------------------------------------------------------------------
// Phase 1: block tile 128x128, BK=32, 8 warps (2m x 4n), warp tile 64x32.
// ---------------------------------------------------------------------------
__global__ __launch_bounds__(256) void xproj_kernel(
    const float* __restrict__ x,
    const float* __restrict__ Wf, const float* __restrict__ bf,
    const float* __restrict__ Wi, const float* __restrict__ bi,
    const float* __restrict__ Wc, const float* __restrict__ bc,
    const float* __restrict__ Wo, const float* __restrict__ bo)
{
    __shared__ uint32_t As[128][36];
    __shared__ uint32_t Bs[128][36];

    const float* Wsel[4] = {Wf, Wi, Wc, Wo};
    const float* bsel[4] = {bf, bi, bc, bo};

    const int tid  = threadIdx.x;
    const int warp = tid >> 5;
    const int lane = tid & 31;
    const int q = lane >> 2, p = lane & 3;
    const int wm = warp >> 2;
    const int wn = warp & 3;
    const int gate = blockIdx.x >> 3;
    const int r0 = (blockIdx.x & 7) * 128;
    const int m0 = blockIdx.y * 128;
    const float* __restrict__ Wg = Wsel[gate];
    const float* __restrict__ bg = bsel[gate];

    const int arow[4] = { tid >> 3, (tid+256) >> 3, (tid+512) >> 3, (tid+768) >> 3 };
    const int ac4 = (tid & 7) * 4;

    float acc[4][4][4];
    #pragma unroll
    for (int mt = 0; mt < 4; ++mt)
        #pragma unroll
        for (int nt = 0; nt < 4; ++nt)
            #pragma unroll
            for (int r = 0; r < 4; ++r) acc[mt][nt][r] = 0.0f;

    float4 ar[4], br[4];

    #pragma unroll
    for (int it = 0; it < 4; ++it) {
        ar[it] = *reinterpret_cast<const float4*>(&x[(size_t)(m0 + arow[it]) * 1024 + ac4]);
        br[it] = *reinterpret_cast<const float4*>(&Wg[(size_t)(r0 + arow[it]) * 2048 + 1024 + ac4]);
    }
    #pragma unroll
    for (int it = 0; it < 4; ++it) {
        uint32_t* wa = &As[arow[it]][ac4];
        wa[0]=f2tf32(ar[it].x); wa[1]=f2tf32(ar[it].y); wa[2]=f2tf32(ar[it].z); wa[3]=f2tf32(ar[it].w);
        uint32_t* wb = &Bs[arow[it]][ac4];
        wb[0]=f2tf32(br[it].x); wb[1]=f2tf32(br[it].y); wb[2]=f2tf32(br[it].z); wb[3]=f2tf32(br[it].w);
    }
    __syncthreads();

    for (int k0 = 0; k0 < 1024; k0 += 32) {
        if (k0 < 992) {
            #pragma unroll
            for (int it = 0; it < 4; ++it) {
                ar[it] = *reinterpret_cast<const float4*>(
                    &x[(size_t)(m0 + arow[it]) * 1024 + k0 + 32 + ac4]);
                br[it] = *reinterpret_cast<const float4*>(
                    &Wg[(size_t)(r0 + arow[it]) * 2048 + 1024 + k0 + 32 + ac4]);
            }
        }

        #pragma unroll
        for (int ks = 0; ks < 4; ++ks) {
            const int kk = ks * 8;
            uint32_t a[4][4];
            #pragma unroll
            for (int mt = 0; mt < 4; ++mt) {
                int rb = wm * 64 + mt * 16 + q;
                a[mt][0] = As[rb][kk + p];
                a[mt][1] = As[rb + 8][kk + p];
                a[mt][2] = As[rb][kk + p + 4];
                a[mt][3] = As[rb + 8][kk + p + 4];
            }
            #pragma unroll
            for (int nt = 0; nt < 4; ++nt) {
                uint32_t bb[2];
                int nr = wn * 32 + nt * 8 + q;
                bb[0] = Bs[nr][kk + p];
                bb[1] = Bs[nr][kk + p + 4];
                #pragma unroll
                for (int mt = 0; mt < 4; ++mt)
                    mma_tf32(acc[mt][nt], a[mt], bb);
            }
        }
        __syncthreads();
        if (k0 < 992) {
            #pragma unroll
            for (int it = 0; it < 4; ++it) {
                uint32_t* wa = &As[arow[it]][ac4];
                wa[0]=f2tf32(ar[it].x); wa[1]=f2tf32(ar[it].y); wa[2]=f2tf32(ar[it].z); wa[3]=f2tf32(ar[it].w);
                uint32_t* wb = &Bs[arow[it]][ac4];
                wb[0]=f2tf32(br[it].x); wb[1]=f2tf32(br[it].y); wb[2]=f2tf32(br[it].z); wb[3]=f2tf32(br[it].w);
            }
            __syncthreads();
        }
    }

    #pragma unroll
    for (int mt = 0; mt < 4; ++mt)
        #pragma unroll
        for (int nt = 0; nt < 4; ++nt)
            #pragma unroll
            for (int r = 0; r < 4; ++r) {
                int row = wm * 64 + mt * 16 + q + ((r >> 1) << 3);
                int col = wn * 32 + nt * 8 + 2 * p + (r & 1);
                int m = m0 + row;
                int b = m >> 8;
                int s = m & 255;
                g_Xp[((size_t)(s * 128 + b) * 4096) + gate * 1024 + r0 + col] =
                    acc[mt][nt][r] + bg[r0 + col];
            }
}

// ---------------------------------------------------------------------------
// Phase 2
// ---------------------------------------------------------------------------
__device__ __forceinline__ void grid_barrier() {
    __threadfence();
    __syncthreads();                 // all threads' stores fenced before CTA arrives
    if (threadIdx.x == 0) {
        unsigned old = atomicAdd(&g_arrive, 1u);
        unsigned target = (old / gridDim.x + 1u) * gridDim.x;
        while (*(volatile unsigned*)&g_arrive < target) {
            __nanosleep(32);
        }
        __threadfence();
    }
    __syncthreads();
}

__global__ void __launch_bounds__(512, 1) lstm_scan_kernel(
    const float* __restrict__ Wf, const float* __restrict__ Wi,
    const float* __restrict__ Wc, const float* __restrict__ Wo,
    float* __restrict__ out)
{
    extern __shared__ uint8_t smem[];
    uint32_t* Ws = reinterpret_cast<uint32_t*>(smem);                       // [32][WS_STRIDE]
    uint32_t* St = reinterpret_cast<uint32_t*>(smem + 32 * WS_STRIDE * 4);  // [16][2][32][ST_STRIDE]
    float*    red = reinterpret_cast<float*>(smem + 32 * WS_STRIDE * 4);    // aliased [3][128][33]

    const float* Wsel[4] = {Wf, Wi, Wc, Wo};
    const int tid  = threadIdx.x;
    const int warp = tid >> 5;
    const int lane = tid & 31;
    const int q = lane >> 2, p = lane & 3;
    const int mg = warp & 3;     // m-group: batches mg*32..+31
    const int km = warp >> 2;    // k-group: k cols km*256..+255
    const int j0 = blockIdx.x * 8;

    uint32_t* Stw = St + warp * ST_WORDS_PER_WARP;             // this warp's slab
    const uint32_t st_base = (uint32_t)__cvta_generic_to_shared(Stw);

    // Load Wh slice as tf32
    for (int idx = tid; idx < 32 * 256; idx += 512) {
        int cc = idx >> 8;
        int k4 = (idx & 255) * 4;
        int g = cc >> 3, jj = cc & 7;
        const float* Wg = Wsel[g];
        float4 v = *reinterpret_cast<const float4*>(&Wg[(size_t)(j0 + jj) * 2048 + k4]);
        uint32_t* wr = &Ws[cc * WS_STRIDE + k4];
        wr[0]=f2tf32(v.x); wr[1]=f2tf32(v.y); wr[2]=f2tf32(v.z); wr[3]=f2tf32(v.w);
    }
    for (int idx = tid; idx < 1024; idx += 512) {
        int b = idx >> 3, jj = idx & 7;
        g_h[b * 1024 + j0 + jj] = 0u;
    }
    float cst[8];
    #pragma unroll
    for (int i = 0; i < 8; ++i) cst[i] = 0.0f;

    // per-lane staging source row (batch) and dst row offset
    const int srcrow = mg * 32 + lane;          // batch this lane stages
    const uint32_t dst_row_off = (uint32_t)(lane * ST_STRIDE) << 2;

    grid_barrier();

    for (int t = 0; t < 256; ++t) {
        const uint32_t* __restrict__ hin = &g_h[(t & 1) * (128 * 1024)];
        uint32_t* __restrict__ hout = &g_h[((t + 1) & 1) * (128 * 1024)];
        const uint32_t* __restrict__ hsrc = hin + (size_t)srcrow * 1024 + km * 256;

        float acc[2][4][4];
        #pragma unroll
        for (int mt = 0; mt < 2; ++mt)
            #pragma unroll
            for (int nt = 0; nt < 4; ++nt)
                #pragma unroll
                for (int r = 0; r < 4; ++r) acc[mt][nt][r] = 0.0f;

        // prologue: stage chunk 0 into buf 0 (warp-private)
        #pragma unroll
        for (int j = 0; j < 4; ++j) {
            uint32_t dsm = st_base + dst_row_off + (uint32_t)(j * 16);
            asm volatile("cp.async.cg.shared.global [%0], [%1], 16;"
                         :: "r"(dsm), "l"(hsrc + j * 4));
        }
        asm volatile("cp.async.commit_group;");

        for (int c = 0; c < 16; ++c) {
            // issue next chunk into other buffer (prev reads done: syncwarp at loop end)
            if (c < 15) {
                uint32_t boff = (uint32_t)(((c + 1) & 1) * ST_WORDS_PER_BUF) << 2;
                const uint32_t* src = hsrc + (c + 1) * 16;
                #pragma unroll
                for (int j = 0; j < 4; ++j) {
                    uint32_t dsm = st_base + boff + dst_row_off + (uint32_t)(j * 16);
                    asm volatile("cp.async.cg.shared.global [%0], [%1], 16;"
                                 :: "r"(dsm), "l"(src + j * 4));
                }
                asm volatile("cp.async.commit_group;");
                asm volatile("cp.async.wait_group 1;");
            } else {
                asm volatile("cp.async.wait_group 0;");
            }
            __syncwarp();   // chunk c data visible across lanes

            const uint32_t* Ab = Stw + (c & 1) * ST_WORDS_PER_BUF;
            #pragma unroll
            for (int s = 0; s < 2; ++s) {
                const int kk = s * 8;
                const int kg = km * 256 + c * 16 + kk;
                uint32_t a[2][4];
                #pragma unroll
                for (int mt = 0; mt < 2; ++mt) {
                    int rb = mt * 16 + q;
                    a[mt][0] = Ab[rb * ST_STRIDE + kk + p];
                    a[mt][1] = Ab[(rb + 8) * ST_STRIDE + kk + p];
                    a[mt][2] = Ab[rb * ST_STRIDE + kk + p + 4];
                    a[mt][3] = Ab[(rb + 8) * ST_STRIDE + kk + p + 4];
                }
                #pragma unroll
                for (int nt = 0; nt < 4; ++nt) {
                    uint32_t bb[2];
                    int nr = nt * 8 + q;
                    bb[0] = Ws[nr * WS_STRIDE + kg + p];
                    bb[1] = Ws[nr * WS_STRIDE + kg + p + 4];
                    mma_tf32(acc[0][nt], a[0], bb);
                    mma_tf32(acc[1][nt], a[1], bb);
                }
            }
            __syncwarp();   // reads done before next iteration overwrites buffer
        }

        __syncthreads();    // all warps done reading staging (red aliases it)

        // 4-way k reduction through smem
        if (km != 0) {
            float* w = &red[((km - 1) * 128 + mg * 32 + lane) * 33];
            #pragma unroll
            for (int mt = 0; mt < 2; ++mt)
                #pragma unroll
                for (int nt = 0; nt < 4; ++nt)
                    #pragma unroll
                    for (int r = 0; r < 4; ++r)
                        w[mt * 16 + nt * 4 + r] = acc[mt][nt][r];
        }
        __syncthreads();

        if (km == 0) {
            // Xp loads (latency overlapped with partial-sum LDS below)
            float2 xp[4][4];
            #pragma unroll
            for (int rr = 0; rr < 4; ++rr) {
                int row = mg * 32 + q + rr * 8;
                size_t base = ((size_t)(t * 128 + row)) * 4096 + j0 + 2 * p;
                #pragma unroll
                for (int g = 0; g < 4; ++g)
                    xp[rr][g] = __ldg(reinterpret_cast<const float2*>(&g_Xp[base + g * 1024]));
            }
            #pragma unroll
            for (int kq = 0; kq < 3; ++kq) {
                const float* w = &red[(kq * 128 + mg * 32 + lane) * 33];
                #pragma unroll
                for (int mt = 0; mt < 2; ++mt)
                    #pragma unroll
                    for (int nt = 0; nt < 4; ++nt)
                        #pragma unroll
                        for (int r = 0; r < 4; ++r)
                            acc[mt][nt][r] += w[mt * 16 + nt * 4 + r];
            }

            #pragma unroll
            for (int mt = 0; mt < 2; ++mt)
                #pragma unroll
                for (int r = 0; r < 4; ++r) {
                    int rr = mt * 2 + (r >> 1);
                    int row = mg * 32 + q + rr * 8;
                    int jj = 2 * p + (r & 1);
                    float xf = (r & 1) ? xp[rr][0].y : xp[rr][0].x;
                    float xi = (r & 1) ? xp[rr][1].y : xp[rr][1].x;
                    float xg = (r & 1) ? xp[rr][2].y : xp[rr][2].x;
                    float xo = (r & 1) ? xp[rr][3].y : xp[rr][3].x;
                    float fg = sigm(acc[mt][0][r] + xf);
                    float ig = sigm(acc[mt][1][r] + xi);
                    float gg = tanhf(acc[mt][2][r] + xg);
                    float og = sigm(acc[mt][3][r] + xo);
                    float cnew = cst[mt * 4 + r] * fg + ig * gg;
                    cst[mt * 4 + r] = cnew;
                    float hnew = tanhf(cnew) * og;
                    hout[row * 1024 + j0 + jj] = f2tf32(hnew);
                    out[(size_t)row * (256 * 1024) + t * 1024 + j0 + jj] = hnew;
                }
        }
        grid_barrier();
    }
}

// ---------------------------------------------------------------------------
extern "C" void kernel_launch(void* const* d_in, const int* in_sizes, int n_in,
                              void* d_out, int out_size) {
    const float* x  = (const float*)d_in[0];
    const float* Wf = (const float*)d_in[1];
    const float* bf = (const float*)d_in[2];
    const float* Wi = (const float*)d_in[3];
    const float* bi = (const float*)d_in[4];
    const float* Wc = (const float*)d_in[5];
    const float* bc = (const float*)d_in[6];
    const float* Wo = (const float*)d_in[7];
    const float* bo = (const float*)d_in[8];
    float* out = (float*)d_out;

    cudaFuncSetAttribute(lstm_scan_kernel,
                         cudaFuncAttributeMaxDynamicSharedMemorySize, SMEM2_BYTES);

    dim3 g1(4096 / 128, 32768 / 128);
    xproj_kernel<<<g1, 256>>>(x, Wf, bf, Wi, bi, Wc, bc, Wo, bo);
    lstm_scan_kernel<<<NBLK2, 512, SMEM2_BYTES>>>(Wf, Wi, Wc, Wo, out);
}

// round 6
// speedup vs baseline: 1.2078x; 1.2078x over previous
#include <cuda_runtime.h>
#include <cuda_bf16.h>
#include <cstdint>
#include <math.h>

// LSTM B=128, S=256, I=1024, H=1024. out[b,s,h] fp32.
// Phase 1: Xp[s][b][4H] = x @ Wx^T + bias (tf32 mma, 128x128 tiles, reg-pipelined)
// Phase 2: persistent 128-CTA scan, 256 thr, 4(m)x2(k) warps, block-wide cp.async
//          double-buffered staging, frag-to-reg early-release chunk body.

#define NBLK2 128
#define WS_STRIDE 1028               // 1024 + 4 pad (u32)
#define AS_STRIDE 68                 // 64 + 4 pad (u32)
#define SMEM2_BYTES (32*WS_STRIDE*4 + 2*128*AS_STRIDE*4)   // 201,216 B

__device__ __align__(16) float    g_Xp[(size_t)256 * 128 * 4096];  // 512 MB
__device__ __align__(16) uint32_t g_h[2 * 128 * 1024];             // h as tf32 bits
__device__ unsigned g_arrive = 0;

__device__ __forceinline__ uint32_t f2tf32(float f) {
    uint32_t u;
    asm volatile("cvt.rna.tf32.f32 %0, %1;" : "=r"(u) : "f"(f));
    return u;
}

__device__ __forceinline__ void mma_tf32(float d[4], const uint32_t a[4], const uint32_t b[2]) {
    asm volatile(
        "mma.sync.aligned.m16n8k8.row.col.f32.tf32.tf32.f32 "
        "{%0,%1,%2,%3},{%4,%5,%6,%7},{%8,%9},{%0,%1,%2,%3};"
        : "+f"(d[0]), "+f"(d[1]), "+f"(d[2]), "+f"(d[3])
        : "r"(a[0]), "r"(a[1]), "r"(a[2]), "r"(a[3]), "r"(b[0]), "r"(b[1]));
}

__device__ __forceinline__ float sigm(float x) { return 1.0f / (1.0f + expf(-x)); }

// ---------------------------------------------------------------------------
// Phase 1: block tile 128x128, BK=32, 8 warps (2m x 4n), warp tile 64x32.
// ---------------------------------------------------------------------------
__global__ __launch_bounds__(256) void xproj_kernel(
    const float* __restrict__ x,
    const float* __restrict__ Wf, const float* __restrict__ bf,
    const float* __restrict__ Wi, const float* __restrict__ bi,
    const float* __restrict__ Wc, const float* __restrict__ bc,
    const float* __restrict__ Wo, const float* __restrict__ bo)
{
    __shared__ uint32_t As[128][36];
    __shared__ uint32_t Bs[128][36];

    const float* Wsel[4] = {Wf, Wi, Wc, Wo};
    const float* bsel[4] = {bf, bi, bc, bo};

    const int tid  = threadIdx.x;
    const int warp = tid >> 5;
    const int lane = tid & 31;
    const int q = lane >> 2, p = lane & 3;
    const int wm = warp >> 2;
    const int wn = warp & 3;
    const int gate = blockIdx.x >> 3;
    const int r0 = (blockIdx.x & 7) * 128;
    const int m0 = blockIdx.y * 128;
    const float* __restrict__ Wg = Wsel[gate];
    const float* __restrict__ bg = bsel[gate];

    const int arow[4] = { tid >> 3, (tid+256) >> 3, (tid+512) >> 3, (tid+768) >> 3 };
    const int ac4 = (tid & 7) * 4;

    float acc[4][4][4];
    #pragma unroll
    for (int mt = 0; mt < 4; ++mt)
        #pragma unroll
        for (int nt = 0; nt < 4; ++nt)
            #pragma unroll
            for (int r = 0; r < 4; ++r) acc[mt][nt][r] = 0.0f;

    float4 ar[4], br[4];

    #pragma unroll
    for (int it = 0; it < 4; ++it) {
        ar[it] = *reinterpret_cast<const float4*>(&x[(size_t)(m0 + arow[it]) * 1024 + ac4]);
        br[it] = *reinterpret_cast<const float4*>(&Wg[(size_t)(r0 + arow[it]) * 2048 + 1024 + ac4]);
    }
    #pragma unroll
    for (int it = 0; it < 4; ++it) {
        uint32_t* wa = &As[arow[it]][ac4];
        wa[0]=f2tf32(ar[it].x); wa[1]=f2tf32(ar[it].y); wa[2]=f2tf32(ar[it].z); wa[3]=f2tf32(ar[it].w);
        uint32_t* wb = &Bs[arow[it]][ac4];
        wb[0]=f2tf32(br[it].x); wb[1]=f2tf32(br[it].y); wb[2]=f2tf32(br[it].z); wb[3]=f2tf32(br[it].w);
    }
    __syncthreads();

    for (int k0 = 0; k0 < 1024; k0 += 32) {
        if (k0 < 992) {
            #pragma unroll
            for (int it = 0; it < 4; ++it) {
                ar[it] = *reinterpret_cast<const float4*>(
                    &x[(size_t)(m0 + arow[it]) * 1024 + k0 + 32 + ac4]);
                br[it] = *reinterpret_cast<const float4*>(
                    &Wg[(size_t)(r0 + arow[it]) * 2048 + 1024 + k0 + 32 + ac4]);
            }
        }

        #pragma unroll
        for (int ks = 0; ks < 4; ++ks) {
            const int kk = ks * 8;
            uint32_t a[4][4];
            #pragma unroll
            for (int mt = 0; mt < 4; ++mt) {
                int rb = wm * 64 + mt * 16 + q;
                a[mt][0] = As[rb][kk + p];
                a[mt][1] = As[rb + 8][kk + p];
                a[mt][2] = As[rb][kk + p + 4];
                a[mt][3] = As[rb + 8][kk + p + 4];
            }
            #pragma unroll
            for (int nt = 0; nt < 4; ++nt) {
                uint32_t bb[2];
                int nr = wn * 32 + nt * 8 + q;
                bb[0] = Bs[nr][kk + p];
                bb[1] = Bs[nr][kk + p + 4];
                #pragma unroll
                for (int mt = 0; mt < 4; ++mt)
                    mma_tf32(acc[mt][nt], a[mt], bb);
            }
        }
        __syncthreads();
        if (k0 < 992) {
            #pragma unroll
            for (int it = 0; it < 4; ++it) {
                uint32_t* wa = &As[arow[it]][ac4];
                wa[0]=f2tf32(ar[it].x); wa[1]=f2tf32(ar[it].y); wa[2]=f2tf32(ar[it].z); wa[3]=f2tf32(ar[it].w);
                uint32_t* wb = &Bs[arow[it]][ac4];
                wb[0]=f2tf32(br[it].x); wb[1]=f2tf32(br[it].y); wb[2]=f2tf32(br[it].z); wb[3]=f2tf32(br[it].w);
            }
            __syncthreads();
        }
    }

    #pragma unroll
    for (int mt = 0; mt < 4; ++mt)
        #pragma unroll
        for (int nt = 0; nt < 4; ++nt)
            #pragma unroll
            for (int r = 0; r < 4; ++r) {
                int row = wm * 64 + mt * 16 + q + ((r >> 1) << 3);
                int col = wn * 32 + nt * 8 + 2 * p + (r & 1);
                int m = m0 + row;
                int b = m >> 8;
                int s = m & 255;
                g_Xp[((size_t)(s * 128 + b) * 4096) + gate * 1024 + r0 + col] =
                    acc[mt][nt][r] + bg[r0 + col];
            }
}

// ---------------------------------------------------------------------------
// Phase 2: 256 threads, 8 warps = 4(m) x 2(k). Block-wide staged chunks of 64.
// ---------------------------------------------------------------------------
__device__ __forceinline__ void grid_barrier() {
    __threadfence();
    __syncthreads();
    if (threadIdx.x == 0) {
        unsigned old = atomicAdd(&g_arrive, 1u);
        unsigned target = (old / gridDim.x + 1u) * gridDim.x;
        while (*(volatile unsigned*)&g_arrive < target) {
            __nanosleep(32);
        }
        __threadfence();
    }
    __syncthreads();
}

__global__ void __launch_bounds__(256, 1) lstm_scan_kernel(
    const float* __restrict__ Wf, const float* __restrict__ Wi,
    const float* __restrict__ Wc, const float* __restrict__ Wo,
    float* __restrict__ out)
{
    extern __shared__ uint8_t smem[];
    uint32_t* Ws  = reinterpret_cast<uint32_t*>(smem);                       // [32][WS_STRIDE]
    uint32_t* Asb = reinterpret_cast<uint32_t*>(smem + 32 * WS_STRIDE * 4);  // [2][128][AS_STRIDE]
    float*    red = reinterpret_cast<float*>(smem + 32 * WS_STRIDE * 4);     // aliased [128][33]

    const float* Wsel[4] = {Wf, Wi, Wc, Wo};
    const int tid  = threadIdx.x;
    const int warp = tid >> 5;
    const int lane = tid & 31;
    const int q = lane >> 2, p = lane & 3;
    const int mg = warp & 3;     // m-group
    const int km = warp >> 2;    // k-interleave (0/1)
    const int j0 = blockIdx.x * 8;

    const uint32_t as_base = (uint32_t)__cvta_generic_to_shared(Asb);

    for (int idx = tid; idx < 32 * 256; idx += 256) {
        int cc = idx >> 8;
        int k4 = (idx & 255) * 4;
        int g = cc >> 3, jj = cc & 7;
        const float* Wg = Wsel[g];
        float4 v = *reinterpret_cast<const float4*>(&Wg[(size_t)(j0 + jj) * 2048 + k4]);
        uint32_t* wr = &Ws[cc * WS_STRIDE + k4];
        wr[0]=f2tf32(v.x); wr[1]=f2tf32(v.y); wr[2]=f2tf32(v.z); wr[3]=f2tf32(v.w);
    }
    for (int idx = tid; idx < 1024; idx += 256) {
        int b = idx >> 3, jj = idx & 7;
        g_h[b * 1024 + j0 + jj] = 0u;
    }
    float cst[8];
    #pragma unroll
    for (int i = 0; i < 8; ++i) cst[i] = 0.0f;

    int srow[8], sc4[8];
    #pragma unroll
    for (int it = 0; it < 8; ++it) {
        int idx = tid + 256 * it;
        srow[it] = idx >> 4;
        sc4[it]  = (idx & 15) * 4;
    }

    grid_barrier();

    for (int t = 0; t < 256; ++t) {
        const uint32_t* __restrict__ hin = &g_h[(t & 1) * (128 * 1024)];
        uint32_t* __restrict__ hout = &g_h[((t + 1) & 1) * (128 * 1024)];

        float acc[2][4][4];
        #pragma unroll
        for (int mt = 0; mt < 2; ++mt)
            #pragma unroll
            for (int nt = 0; nt < 4; ++nt)
                #pragma unroll
                for (int r = 0; r < 4; ++r) acc[mt][nt][r] = 0.0f;

        // prologue: stage chunk 0 into buf 0
        #pragma unroll
        for (int it = 0; it < 8; ++it) {
            uint32_t dsm = as_base + ((srow[it] * AS_STRIDE + sc4[it]) << 2);
            const uint32_t* src = hin + srow[it] * 1024 + sc4[it];
            asm volatile("cp.async.cg.shared.global [%0], [%1], 16;" :: "r"(dsm), "l"(src));
        }
        asm volatile("cp.async.commit_group;");

        for (int c = 0; c < 16; ++c) {
            if (c < 15) {
                uint32_t boff = (uint32_t)(((c + 1) & 1) * 128 * AS_STRIDE) << 2;
                #pragma unroll
                for (int it = 0; it < 8; ++it) {
                    uint32_t dsm = as_base + boff + ((srow[it] * AS_STRIDE + sc4[it]) << 2);
                    const uint32_t* src = hin + srow[it] * 1024 + (c + 1) * 64 + sc4[it];
                    asm volatile("cp.async.cg.shared.global [%0], [%1], 16;" :: "r"(dsm), "l"(src));
                }
                asm volatile("cp.async.commit_group;");
                asm volatile("cp.async.wait_group 1;");
            } else {
                asm volatile("cp.async.wait_group 0;");
            }
            __syncthreads();   // chunk c visible to all warps

            // load ALL fragments for this chunk into registers
            const uint32_t* Ab = Asb + (c & 1) * (128 * AS_STRIDE);
            uint32_t afr[4][2][4];
            uint32_t bfr[4][4][2];
            #pragma unroll
            for (int s = 0; s < 4; ++s) {
                const int kk = (2 * s + km) * 8;
                const int kg = c * 64 + kk;
                #pragma unroll
                for (int mt = 0; mt < 2; ++mt) {
                    int rb = mg * 32 + mt * 16 + q;
                    afr[s][mt][0] = Ab[rb * AS_STRIDE + kk + p];
                    afr[s][mt][1] = Ab[(rb + 8) * AS_STRIDE + kk + p];
                    afr[s][mt][2] = Ab[rb * AS_STRIDE + kk + p + 4];
                    afr[s][mt][3] = Ab[(rb + 8) * AS_STRIDE + kk + p + 4];
                }
                #pragma unroll
                for (int nt = 0; nt < 4; ++nt) {
                    int nr = nt * 8 + q;
                    bfr[s][nt][0] = Ws[nr * WS_STRIDE + kg + p];
                    bfr[s][nt][1] = Ws[nr * WS_STRIDE + kg + p + 4];
                }
            }
            __syncthreads();   // buffer free for overwrite; mma runs from regs

            #pragma unroll
            for (int s = 0; s < 4; ++s)
                #pragma unroll
                for (int nt = 0; nt < 4; ++nt) {
                    mma_tf32(acc[0][nt], afr[s][0], bfr[s][nt]);
                    mma_tf32(acc[1][nt], afr[s][1], bfr[s][nt]);
                }
        }

        // 2-way k reduction through smem (aliased over staging; mma used regs only,
        // and all staging reads finished before the last sync above)
        if (km == 1) {
            float* w = &red[(mg * 32 + lane) * 33];
            #pragma unroll
            for (int mt = 0; mt < 2; ++mt)
                #pragma unroll
                for (int nt = 0; nt < 4; ++nt)
                    #pragma unroll
                    for (int r = 0; r < 4; ++r)
                        w[mt * 16 + nt * 4 + r] = acc[mt][nt][r];
        }
        __syncthreads();
        if (km == 0) {
            float2 xp[4][4];
            #pragma unroll
            for (int rr = 0; rr < 4; ++rr) {
                int row = mg * 32 + q + rr * 8;
                size_t base = ((size_t)(t * 128 + row)) * 4096 + j0 + 2 * p;
                #pragma unroll
                for (int g = 0; g < 4; ++g)
                    xp[rr][g] = __ldg(reinterpret_cast<const float2*>(&g_Xp[base + g * 1024]));
            }
            const float* w = &red[(mg * 32 + lane) * 33];
            #pragma unroll
            for (int mt = 0; mt < 2; ++mt)
                #pragma unroll
                for (int nt = 0; nt < 4; ++nt)
                    #pragma unroll
                    for (int r = 0; r < 4; ++r)
                        acc[mt][nt][r] += w[mt * 16 + nt * 4 + r];

            #pragma unroll
            for (int mt = 0; mt < 2; ++mt)
                #pragma unroll
                for (int r = 0; r < 4; ++r) {
                    int rr = mt * 2 + (r >> 1);
                    int row = mg * 32 + q + rr * 8;
                    int jj = 2 * p + (r & 1);
                    float xf = (r & 1) ? xp[rr][0].y : xp[rr][0].x;
                    float xi = (r & 1) ? xp[rr][1].y : xp[rr][1].x;
                    float xg = (r & 1) ? xp[rr][2].y : xp[rr][2].x;
                    float xo = (r & 1) ? xp[rr][3].y : xp[rr][3].x;
                    float fg = sigm(acc[mt][0][r] + xf);
                    float ig = sigm(acc[mt][1][r] + xi);
                    float gg = tanhf(acc[mt][2][r] + xg);
                    float og = sigm(acc[mt][3][r] + xo);
                    float cnew = cst[mt * 4 + r] * fg + ig * gg;
                    cst[mt * 4 + r] = cnew;
                    float hnew = tanhf(cnew) * og;
                    hout[row * 1024 + j0 + jj] = f2tf32(hnew);
                    out[(size_t)row * (256 * 1024) + t * 1024 + j0 + jj] = hnew;
                }
        }
        grid_barrier();
    }
}

// ---------------------------------------------------------------------------
extern "C" void kernel_launch(void* const* d_in, const int* in_sizes, int n_in,
                              void* d_out, int out_size) {
    const float* x  = (const float*)d_in[0];
    const float* Wf = (const float*)d_in[1];
    const float* bf = (const float*)d_in[2];
    const float* Wi = (const float*)d_in[3];
    const float* bi = (const float*)d_in[4];
    const float* Wc = (const float*)d_in[5];
    const float* bc = (const float*)d_in[6];
    const float* Wo = (const float*)d_in[7];
    const float* bo = (const float*)d_in[8];
    float* out = (float*)d_out;

    cudaFuncSetAttribute(lstm_scan_kernel,
                         cudaFuncAttributeMaxDynamicSharedMemorySize, SMEM2_BYTES);

    dim3 g1(4096 / 128, 32768 / 128);
    xproj_kernel<<<g1, 256>>>(x, Wf, bf, Wi, bi, Wc, bc, Wo, bo);
    lstm_scan_kernel<<<NBLK2, 256, SMEM2_BYTES>>>(Wf, Wi, Wc, Wo, out);
}

// round 7
// speedup vs baseline: 1.6275x; 1.3475x over previous
#include <cuda_runtime.h>
#include <cuda_fp16.h>
#include <cstdint>
#include <math.h>

// LSTM B=128, S=256, I=1024, H=1024. out[b,s,h] fp32.
// Phase 1: Xp[s][b][4H] = x @ Wx^T + bias (tf32 mma, 128x128 tiles, reg-pipelined)
// Phase 2: persistent 128-CTA scan, 256 thr, 4(m)x2(k) warps, fp16 h/Wh,
//          m16n8k16 mma (fp32 accum), 128-col cp.async chunks, early-release.

#define NBLK2 128
#define WS2_STRIDE 516               // 512 + 4 pad (u32) ; row = 1024 fp16
#define AS2_STRIDE 68                // 64 + 4 pad (u32)  ; row = 128 fp16 chunk
#define SMEM2_BYTES (32*WS2_STRIDE*4 + 2*128*AS2_STRIDE*4)   // 66048 + 69632 = 135680

__device__ __align__(16) float    g_Xp[(size_t)256 * 128 * 4096];  // 512 MB
__device__ __align__(16) __half   g_h[2 * 128 * 1024];             // h fp16, dbl buf
__device__ unsigned g_arrive = 0;

__device__ __forceinline__ uint32_t f2tf32(float f) {
    uint32_t u;
    asm volatile("cvt.rna.tf32.f32 %0, %1;" : "=r"(u) : "f"(f));
    return u;
}

__device__ __forceinline__ void mma_tf32(float d[4], const uint32_t a[4], const uint32_t b[2]) {
    asm volatile(
        "mma.sync.aligned.m16n8k8.row.col.f32.tf32.tf32.f32 "
        "{%0,%1,%2,%3},{%4,%5,%6,%7},{%8,%9},{%0,%1,%2,%3};"
        : "+f"(d[0]), "+f"(d[1]), "+f"(d[2]), "+f"(d[3])
        : "r"(a[0]), "r"(a[1]), "r"(a[2]), "r"(a[3]), "r"(b[0]), "r"(b[1]));
}

__device__ __forceinline__ void mma_f16(float d[4], const uint32_t a[4], const uint32_t b[2]) {
    asm volatile(
        "mma.sync.aligned.m16n8k16.row.col.f32.f16.f16.f32 "
        "{%0,%1,%2,%3},{%4,%5,%6,%7},{%8,%9},{%0,%1,%2,%3};"
        : "+f"(d[0]), "+f"(d[1]), "+f"(d[2]), "+f"(d[3])
        : "r"(a[0]), "r"(a[1]), "r"(a[2]), "r"(a[3]), "r"(b[0]), "r"(b[1]));
}

__device__ __forceinline__ float sigm(float x) { return 1.0f / (1.0f + expf(-x)); }

// ---------------------------------------------------------------------------
// Phase 1: block tile 128x128, BK=32, 8 warps (2m x 4n), warp tile 64x32. (tf32)
// ---------------------------------------------------------------------------
__global__ __launch_bounds__(256) void xproj_kernel(
    const float* __restrict__ x,
    const float* __restrict__ Wf, const float* __restrict__ bf,
    const float* __restrict__ Wi, const float* __restrict__ bi,
    const float* __restrict__ Wc, const float* __restrict__ bc,
    const float* __restrict__ Wo, const float* __restrict__ bo)
{
    __shared__ uint32_t As[128][36];
    __shared__ uint32_t Bs[128][36];

    const float* Wsel[4] = {Wf, Wi, Wc, Wo};
    const float* bsel[4] = {bf, bi, bc, bo};

    const int tid  = threadIdx.x;
    const int warp = tid >> 5;
    const int lane = tid & 31;
    const int q = lane >> 2, p = lane & 3;
    const int wm = warp >> 2;
    const int wn = warp & 3;
    const int gate = blockIdx.x >> 3;
    const int r0 = (blockIdx.x & 7) * 128;
    const int m0 = blockIdx.y * 128;
    const float* __restrict__ Wg = Wsel[gate];
    const float* __restrict__ bg = bsel[gate];

    const int arow[4] = { tid >> 3, (tid+256) >> 3, (tid+512) >> 3, (tid+768) >> 3 };
    const int ac4 = (tid & 7) * 4;

    float acc[4][4][4];
    #pragma unroll
    for (int mt = 0; mt < 4; ++mt)
        #pragma unroll
        for (int nt = 0; nt < 4; ++nt)
            #pragma unroll
            for (int r = 0; r < 4; ++r) acc[mt][nt][r] = 0.0f;

    float4 ar[4], br[4];

    #pragma unroll
    for (int it = 0; it < 4; ++it) {
        ar[it] = *reinterpret_cast<const float4*>(&x[(size_t)(m0 + arow[it]) * 1024 + ac4]);
        br[it] = *reinterpret_cast<const float4*>(&Wg[(size_t)(r0 + arow[it]) * 2048 + 1024 + ac4]);
    }
    #pragma unroll
    for (int it = 0; it < 4; ++it) {
        uint32_t* wa = &As[arow[it]][ac4];
        wa[0]=f2tf32(ar[it].x); wa[1]=f2tf32(ar[it].y); wa[2]=f2tf32(ar[it].z); wa[3]=f2tf32(ar[it].w);
        uint32_t* wb = &Bs[arow[it]][ac4];
        wb[0]=f2tf32(br[it].x); wb[1]=f2tf32(br[it].y); wb[2]=f2tf32(br[it].z); wb[3]=f2tf32(br[it].w);
    }
    __syncthreads();

    for (int k0 = 0; k0 < 1024; k0 += 32) {
        if (k0 < 992) {
            #pragma unroll
            for (int it = 0; it < 4; ++it) {
                ar[it] = *reinterpret_cast<const float4*>(
                    &x[(size_t)(m0 + arow[it]) * 1024 + k0 + 32 + ac4]);
                br[it] = *reinterpret_cast<const float4*>(
                    &Wg[(size_t)(r0 + arow[it]) * 2048 + 1024 + k0 + 32 + ac4]);
            }
        }

        #pragma unroll
        for (int ks = 0; ks < 4; ++ks) {
            const int kk = ks * 8;
            uint32_t a[4][4];
            #pragma unroll
            for (int mt = 0; mt < 4; ++mt) {
                int rb = wm * 64 + mt * 16 + q;
                a[mt][0] = As[rb][kk + p];
                a[mt][1] = As[rb + 8][kk + p];
                a[mt][2] = As[rb][kk + p + 4];
                a[mt][3] = As[rb + 8][kk + p + 4];
            }
            #pragma unroll
            for (int nt = 0; nt < 4; ++nt) {
                uint32_t bb[2];
                int nr = wn * 32 + nt * 8 + q;
                bb[0] = Bs[nr][kk + p];
                bb[1] = Bs[nr][kk + p + 4];
                #pragma unroll
                for (int mt = 0; mt < 4; ++mt)
                    mma_tf32(acc[mt][nt], a[mt], bb);
            }
        }
        __syncthreads();
        if (k0 < 992) {
            #pragma unroll
            for (int it = 0; it < 4; ++it) {
                uint32_t* wa = &As[arow[it]][ac4];
                wa[0]=f2tf32(ar[it].x); wa[1]=f2tf32(ar[it].y); wa[2]=f2tf32(ar[it].z); wa[3]=f2tf32(ar[it].w);
                uint32_t* wb = &Bs[arow[it]][ac4];
                wb[0]=f2tf32(br[it].x); wb[1]=f2tf32(br[it].y); wb[2]=f2tf32(br[it].z); wb[3]=f2tf32(br[it].w);
            }
            __syncthreads();
        }
    }

    #pragma unroll
    for (int mt = 0; mt < 4; ++mt)
        #pragma unroll
        for (int nt = 0; nt < 4; ++nt)
            #pragma unroll
            for (int r = 0; r < 4; ++r) {
                int row = wm * 64 + mt * 16 + q + ((r >> 1) << 3);
                int col = wn * 32 + nt * 8 + 2 * p + (r & 1);
                int m = m0 + row;
                int b = m >> 8;
                int s = m & 255;
                g_Xp[((size_t)(s * 128 + b) * 4096) + gate * 1024 + r0 + col] =
                    acc[mt][nt][r] + bg[r0 + col];
            }
}

// ---------------------------------------------------------------------------
// Phase 2: 256 threads, 8 warps = 4(m) x 2(k). fp16 path, 8 chunks of 128 cols.
// ---------------------------------------------------------------------------
__device__ __forceinline__ void grid_barrier() {
    __threadfence();
    __syncthreads();
    if (threadIdx.x == 0) {
        unsigned old = atomicAdd(&g_arrive, 1u);
        unsigned target = (old / gridDim.x + 1u) * gridDim.x;
        while (*(volatile unsigned*)&g_arrive < target) {
            __nanosleep(32);
        }
        __threadfence();
    }
    __syncthreads();
}

__global__ void __launch_bounds__(256, 1) lstm_scan_kernel(
    const float* __restrict__ Wf, const float* __restrict__ Wi,
    const float* __restrict__ Wc, const float* __restrict__ Wo,
    float* __restrict__ out)
{
    extern __shared__ uint8_t smem[];
    uint32_t* Ws  = reinterpret_cast<uint32_t*>(smem);                        // [32][WS2_STRIDE] (fp16x2)
    uint32_t* Asb = reinterpret_cast<uint32_t*>(smem + 32 * WS2_STRIDE * 4);  // [2][128][AS2_STRIDE]
    float*    red = reinterpret_cast<float*>(smem + 32 * WS2_STRIDE * 4);     // aliased [128][33]

    const float* Wsel[4] = {Wf, Wi, Wc, Wo};
    const int tid  = threadIdx.x;
    const int warp = tid >> 5;
    const int lane = tid & 31;
    const int q = lane >> 2, p = lane & 3;
    const int mg = warp & 3;     // m-group (32 batches)
    const int km = warp >> 2;    // k-interleave (0/1)
    const int j0 = blockIdx.x * 8;

    const uint32_t as_base = (uint32_t)__cvta_generic_to_shared(Asb);

    // Load Wh slice as fp16 pairs: Ws[gate*8+jj][k/2] = half2(W[k], W[k+1])
    for (int idx = tid; idx < 32 * 256; idx += 256) {
        int cc = idx >> 8;               // row 0..31
        int k4 = (idx & 255) * 4;        // fp32 col
        int g = cc >> 3, jj = cc & 7;
        const float* Wg = Wsel[g];
        float4 v = *reinterpret_cast<const float4*>(&Wg[(size_t)(j0 + jj) * 2048 + k4]);
        __half2 h0 = __floats2half2_rn(v.x, v.y);
        __half2 h1 = __floats2half2_rn(v.z, v.w);
        uint32_t* wr = &Ws[cc * WS2_STRIDE + (k4 >> 1)];
        wr[0] = *reinterpret_cast<uint32_t*>(&h0);
        wr[1] = *reinterpret_cast<uint32_t*>(&h1);
    }
    for (int idx = tid; idx < 1024; idx += 256) {
        int b = idx >> 3, jj = idx & 7;
        g_h[b * 1024 + j0 + jj] = __float2half_rn(0.0f);
    }
    float cst[8];
    #pragma unroll
    for (int i = 0; i < 8; ++i) cst[i] = 0.0f;

    // staging: chunk = 128 rows x 128 fp16 = 32KB; per thread 8 x 16B
    int srow[8], sc4[8];
    #pragma unroll
    for (int it = 0; it < 8; ++it) {
        int idx = tid + 256 * it;
        srow[it] = idx >> 4;             // 16 ops per row
        sc4[it]  = (idx & 15) * 4;       // u32 offset within chunk row (0..60)
    }

    grid_barrier();

    for (int t = 0; t < 256; ++t) {
        const uint32_t* __restrict__ hin =
            reinterpret_cast<const uint32_t*>(&g_h[(t & 1) * (128 * 1024)]);
        __half* __restrict__ hout = &g_h[((t + 1) & 1) * (128 * 1024)];

        float acc[2][4][4];
        #pragma unroll
        for (int mt = 0; mt < 2; ++mt)
            #pragma unroll
            for (int nt = 0; nt < 4; ++nt)
                #pragma unroll
                for (int r = 0; r < 4; ++r) acc[mt][nt][r] = 0.0f;

        // prologue: stage chunk 0 into buf 0
        #pragma unroll
        for (int it = 0; it < 8; ++it) {
            uint32_t dsm = as_base + ((srow[it] * AS2_STRIDE + sc4[it]) << 2);
            const uint32_t* src = hin + srow[it] * 512 + sc4[it];
            asm volatile("cp.async.cg.shared.global [%0], [%1], 16;" :: "r"(dsm), "l"(src));
        }
        asm volatile("cp.async.commit_group;");

        for (int c = 0; c < 8; ++c) {
            if (c < 7) {
                uint32_t boff = (uint32_t)(((c + 1) & 1) * 128 * AS2_STRIDE) << 2;
                #pragma unroll
                for (int it = 0; it < 8; ++it) {
                    uint32_t dsm = as_base + boff + ((srow[it] * AS2_STRIDE + sc4[it]) << 2);
                    const uint32_t* src = hin + srow[it] * 512 + (c + 1) * 64 + sc4[it];
                    asm volatile("cp.async.cg.shared.global [%0], [%1], 16;" :: "r"(dsm), "l"(src));
                }
                asm volatile("cp.async.commit_group;");
                asm volatile("cp.async.wait_group 1;");
            } else {
                asm volatile("cp.async.wait_group 0;");
            }
            __syncthreads();   // chunk c visible

            // load all fragments for this chunk into registers
            const uint32_t* Ab = Asb + (c & 1) * (128 * AS2_STRIDE);
            uint32_t afr[4][2][4];
            uint32_t bfr[4][4][2];
            #pragma unroll
            for (int s = 0; s < 4; ++s) {
                const int fi = 2 * s + km;              // k16-frag index in chunk (0..7)
                const int au = fi * 8 + p;              // u32 col in staging row
                const int bu = c * 64 + fi * 8 + p;     // u32 col in Ws row
                #pragma unroll
                for (int mt = 0; mt < 2; ++mt) {
                    int rb = mg * 32 + mt * 16 + q;
                    afr[s][mt][0] = Ab[rb * AS2_STRIDE + au];
                    afr[s][mt][1] = Ab[(rb + 8) * AS2_STRIDE + au];
                    afr[s][mt][2] = Ab[rb * AS2_STRIDE + au + 4];
                    afr[s][mt][3] = Ab[(rb + 8) * AS2_STRIDE + au + 4];
                }
                #pragma unroll
                for (int nt = 0; nt < 4; ++nt) {
                    int nr = nt * 8 + q;
                    bfr[s][nt][0] = Ws[nr * WS2_STRIDE + bu];
                    bfr[s][nt][1] = Ws[nr * WS2_STRIDE + bu + 4];
                }
            }
            __syncthreads();   // buffer free; mma runs from regs, overlaps next copy

            #pragma unroll
            for (int s = 0; s < 4; ++s)
                #pragma unroll
                for (int nt = 0; nt < 4; ++nt) {
                    mma_f16(acc[0][nt], afr[s][0], bfr[s][nt]);
                    mma_f16(acc[1][nt], afr[s][1], bfr[s][nt]);
                }
        }

        // 2-way k reduction through smem (aliased; staging reads done pre-sync)
        if (km == 1) {
            float* w = &red[(mg * 32 + lane) * 33];
            #pragma unroll
            for (int mt = 0; mt < 2; ++mt)
                #pragma unroll
                for (int nt = 0; nt < 4; ++nt)
                    #pragma unroll
                    for (int r = 0; r < 4; ++r)
                        w[mt * 16 + nt * 4 + r] = acc[mt][nt][r];
        }
        __syncthreads();
        if (km == 0) {
            float2 xp[4][4];
            #pragma unroll
            for (int rr = 0; rr < 4; ++rr) {
                int row = mg * 32 + q + rr * 8;
                size_t base = ((size_t)(t * 128 + row)) * 4096 + j0 + 2 * p;
                #pragma unroll
                for (int g = 0; g < 4; ++g)
                    xp[rr][g] = __ldg(reinterpret_cast<const float2*>(&g_Xp[base + g * 1024]));
            }
            const float* w = &red[(mg * 32 + lane) * 33];
            #pragma unroll
            for (int mt = 0; mt < 2; ++mt)
                #pragma unroll
                for (int nt = 0; nt < 4; ++nt)
                    #pragma unroll
                    for (int r = 0; r < 4; ++r)
                        acc[mt][nt][r] += w[mt * 16 + nt * 4 + r];

            #pragma unroll
            for (int mt = 0; mt < 2; ++mt)
                #pragma unroll
                for (int r = 0; r < 4; ++r) {
                    int rr = mt * 2 + (r >> 1);
                    int row = mg * 32 + q + rr * 8;
                    int jj = 2 * p + (r & 1);
                    float xf = (r & 1) ? xp[rr][0].y : xp[rr][0].x;
                    float xi = (r & 1) ? xp[rr][1].y : xp[rr][1].x;
                    float xg = (r & 1) ? xp[rr][2].y : xp[rr][2].x;
                    float xo = (r & 1) ? xp[rr][3].y : xp[rr][3].x;
                    float fg = sigm(acc[mt][0][r] + xf);
                    float ig = sigm(acc[mt][1][r] + xi);
                    float gg = tanhf(acc[mt][2][r] + xg);
                    float og = sigm(acc[mt][3][r] + xo);
                    float cnew = cst[mt * 4 + r] * fg + ig * gg;
                    cst[mt * 4 + r] = cnew;
                    float hnew = tanhf(cnew) * og;
                    hout[row * 1024 + j0 + jj] = __float2half_rn(hnew);
                    out[(size_t)row * (256 * 1024) + t * 1024 + j0 + jj] = hnew;
                }
        }
        grid_barrier();
    }
}

// ---------------------------------------------------------------------------
extern "C" void kernel_launch(void* const* d_in, const int* in_sizes, int n_in,
                              void* d_out, int out_size) {
    const float* x  = (const float*)d_in[0];
    const float* Wf = (const float*)d_in[1];
    const float* bf = (const float*)d_in[2];
    const float* Wi = (const float*)d_in[3];
    const float* bi = (const float*)d_in[4];
    const float* Wc = (const float*)d_in[5];
    const float* bc = (const float*)d_in[6];
    const float* Wo = (const float*)d_in[7];
    const float* bo = (const float*)d_in[8];
    float* out = (float*)d_out;

    cudaFuncSetAttribute(lstm_scan_kernel,
                         cudaFuncAttributeMaxDynamicSharedMemorySize, SMEM2_BYTES);

    dim3 g1(4096 / 128, 32768 / 128);
    xproj_kernel<<<g1, 256>>>(x, Wf, bf, Wi, bi, Wc, bc, Wo, bo);
    lstm_scan_kernel<<<NBLK2, 256, SMEM2_BYTES>>>(Wf, Wi, Wc, Wo, out);
}

// round 8
// speedup vs baseline: 1.9152x; 1.1768x over previous
#include <cuda_runtime.h>
#include <cuda_fp16.h>
#include <cstdint>
#include <math.h>

// LSTM B=128, S=256, I=1024, H=1024. out[b,s,h] fp32.
// Phase 1: Xp = x @ Wx^T + bias (fp16 mma m16n8k16, fp32 accum, 128x128 tiles)
// Phase 2: persistent 128-CTA scan, fp16 h/Wh, triple-buffered cp.async chunks.

#define NBLK2 128
#define WS2_STRIDE 516               // 512 + 4 pad (u32) ; row = 1024 fp16
#define AS2_STRIDE 68                // 64 + 4 pad (u32)  ; row = 128 fp16 chunk
#define SMEM2_BYTES (32*WS2_STRIDE*4 + 3*128*AS2_STRIDE*4)   // 66048 + 104448 = 170496

__device__ __align__(16) float    g_Xp[(size_t)256 * 128 * 4096];  // 512 MB
__device__ __align__(16) __half   g_h[2 * 128 * 1024];             // h fp16, dbl buf
__device__ unsigned g_arrive = 0;

__device__ __forceinline__ uint32_t packh2(float a, float b) {
    __half2 h = __floats2half2_rn(a, b);
    return *reinterpret_cast<uint32_t*>(&h);
}

__device__ __forceinline__ void mma_f16(float d[4], const uint32_t a[4], const uint32_t b[2]) {
    asm volatile(
        "mma.sync.aligned.m16n8k16.row.col.f32.f16.f16.f32 "
        "{%0,%1,%2,%3},{%4,%5,%6,%7},{%8,%9},{%0,%1,%2,%3};"
        : "+f"(d[0]), "+f"(d[1]), "+f"(d[2]), "+f"(d[3])
        : "r"(a[0]), "r"(a[1]), "r"(a[2]), "r"(a[3]), "r"(b[0]), "r"(b[1]));
}

__device__ __forceinline__ float sigm(float x) { return 1.0f / (1.0f + expf(-x)); }

// ---------------------------------------------------------------------------
// Phase 1: block tile 128x128, BK=32 (fp16), 8 warps (2m x 4n), warp 64x32.
// ---------------------------------------------------------------------------
__global__ __launch_bounds__(256) void xproj_kernel(
    const float* __restrict__ x,
    const float* __restrict__ Wf, const float* __restrict__ bf,
    const float* __restrict__ Wi, const float* __restrict__ bi,
    const float* __restrict__ Wc, const float* __restrict__ bc,
    const float* __restrict__ Wo, const float* __restrict__ bo)
{
    __shared__ uint32_t As[128][20];   // 32 fp16 = 16 u32 + 4 pad
    __shared__ uint32_t Bs[128][20];

    const float* Wsel[4] = {Wf, Wi, Wc, Wo};
    const float* bsel[4] = {bf, bi, bc, bo};

    const int tid  = threadIdx.x;
    const int warp = tid >> 5;
    const int lane = tid & 31;
    const int q = lane >> 2, p = lane & 3;
    const int wm = warp >> 2;
    const int wn = warp & 3;
    const int gate = blockIdx.x >> 3;
    const int r0 = (blockIdx.x & 7) * 128;
    const int m0 = blockIdx.y * 128;
    const float* __restrict__ Wg = Wsel[gate];
    const float* __restrict__ bg = bsel[gate];

    const int arow[4] = { tid >> 3, (tid+256) >> 3, (tid+512) >> 3, (tid+768) >> 3 };
    const int ac4 = (tid & 7) * 4;     // fp32 col
    const int acu = (tid & 7) * 2;     // u32 (half2) col

    float acc[4][4][4];
    #pragma unroll
    for (int mt = 0; mt < 4; ++mt)
        #pragma unroll
        for (int nt = 0; nt < 4; ++nt)
            #pragma unroll
            for (int r = 0; r < 4; ++r) acc[mt][nt][r] = 0.0f;

    float4 ar[4], br[4];

    #pragma unroll
    for (int it = 0; it < 4; ++it) {
        ar[it] = *reinterpret_cast<const float4*>(&x[(size_t)(m0 + arow[it]) * 1024 + ac4]);
        br[it] = *reinterpret_cast<const float4*>(&Wg[(size_t)(r0 + arow[it]) * 2048 + 1024 + ac4]);
    }
    #pragma unroll
    for (int it = 0; it < 4; ++it) {
        uint32_t* wa = &As[arow[it]][acu];
        wa[0] = packh2(ar[it].x, ar[it].y); wa[1] = packh2(ar[it].z, ar[it].w);
        uint32_t* wb = &Bs[arow[it]][acu];
        wb[0] = packh2(br[it].x, br[it].y); wb[1] = packh2(br[it].z, br[it].w);
    }
    __syncthreads();

    for (int k0 = 0; k0 < 1024; k0 += 32) {
        if (k0 < 992) {
            #pragma unroll
            for (int it = 0; it < 4; ++it) {
                ar[it] = *reinterpret_cast<const float4*>(
                    &x[(size_t)(m0 + arow[it]) * 1024 + k0 + 32 + ac4]);
                br[it] = *reinterpret_cast<const float4*>(
                    &Wg[(size_t)(r0 + arow[it]) * 2048 + 1024 + k0 + 32 + ac4]);
            }
        }

        #pragma unroll
        for (int ks = 0; ks < 2; ++ks) {       // two k16 fragments per tile
            const int kk = ks * 8;             // u32 col
            uint32_t a[4][4];
            #pragma unroll
            for (int mt = 0; mt < 4; ++mt) {
                int rb = wm * 64 + mt * 16 + q;
                a[mt][0] = As[rb][kk + p];
                a[mt][1] = As[rb + 8][kk + p];
                a[mt][2] = As[rb][kk + p + 4];
                a[mt][3] = As[rb + 8][kk + p + 4];
            }
            #pragma unroll
            for (int nt = 0; nt < 4; ++nt) {
                uint32_t bb[2];
                int nr = wn * 32 + nt * 8 + q;
                bb[0] = Bs[nr][kk + p];
                bb[1] = Bs[nr][kk + p + 4];
                #pragma unroll
                for (int mt = 0; mt < 4; ++mt)
                    mma_f16(acc[mt][nt], a[mt], bb);
            }
        }
        __syncthreads();
        if (k0 < 992) {
            #pragma unroll
            for (int it = 0; it < 4; ++it) {
                uint32_t* wa = &As[arow[it]][acu];
                wa[0] = packh2(ar[it].x, ar[it].y); wa[1] = packh2(ar[it].z, ar[it].w);
                uint32_t* wb = &Bs[arow[it]][acu];
                wb[0] = packh2(br[it].x, br[it].y); wb[1] = packh2(br[it].z, br[it].w);
            }
            __syncthreads();
        }
    }

    #pragma unroll
    for (int mt = 0; mt < 4; ++mt)
        #pragma unroll
        for (int nt = 0; nt < 4; ++nt)
            #pragma unroll
            for (int r = 0; r < 4; ++r) {
                int row = wm * 64 + mt * 16 + q + ((r >> 1) << 3);
                int col = wn * 32 + nt * 8 + 2 * p + (r & 1);
                int m = m0 + row;
                int b = m >> 8;
                int s = m & 255;
                g_Xp[((size_t)(s * 128 + b) * 4096) + gate * 1024 + r0 + col] =
                    acc[mt][nt][r] + bg[r0 + col];
            }
}

// ---------------------------------------------------------------------------
// Phase 2: 256 threads, 8 warps = 4(m) x 2(k). fp16, 8 chunks of 128 cols,
// TRIPLE buffered: one __syncthreads per chunk.
// ---------------------------------------------------------------------------
__device__ __forceinline__ void grid_barrier() {
    __threadfence();
    __syncthreads();
    if (threadIdx.x == 0) {
        unsigned old = atomicAdd(&g_arrive, 1u);
        unsigned target = (old / gridDim.x + 1u) * gridDim.x;
        while (*(volatile unsigned*)&g_arrive < target) {
            __nanosleep(32);
        }
        __threadfence();
    }
    __syncthreads();
}

__global__ void __launch_bounds__(256, 1) lstm_scan_kernel(
    const float* __restrict__ Wf, const float* __restrict__ Wi,
    const float* __restrict__ Wc, const float* __restrict__ Wo,
    float* __restrict__ out)
{
    extern __shared__ uint8_t smem[];
    uint32_t* Ws  = reinterpret_cast<uint32_t*>(smem);                        // [32][WS2_STRIDE]
    uint32_t* Asb = reinterpret_cast<uint32_t*>(smem + 32 * WS2_STRIDE * 4);  // [3][128][AS2_STRIDE]
    float*    red = reinterpret_cast<float*>(smem + 32 * WS2_STRIDE * 4);     // aliased [128][33]

    const float* Wsel[4] = {Wf, Wi, Wc, Wo};
    const int tid  = threadIdx.x;
    const int warp = tid >> 5;
    const int lane = tid & 31;
    const int q = lane >> 2, p = lane & 3;
    const int mg = warp & 3;
    const int km = warp >> 2;
    const int j0 = blockIdx.x * 8;

    const uint32_t as_base = (uint32_t)__cvta_generic_to_shared(Asb);

    // Load Wh slice as fp16 pairs
    for (int idx = tid; idx < 32 * 256; idx += 256) {
        int cc = idx >> 8;
        int k4 = (idx & 255) * 4;
        int g = cc >> 3, jj = cc & 7;
        const float* Wg = Wsel[g];
        float4 v = *reinterpret_cast<const float4*>(&Wg[(size_t)(j0 + jj) * 2048 + k4]);
        uint32_t* wr = &Ws[cc * WS2_STRIDE + (k4 >> 1)];
        wr[0] = packh2(v.x, v.y);
        wr[1] = packh2(v.z, v.w);
    }
    for (int idx = tid; idx < 1024; idx += 256) {
        int b = idx >> 3, jj = idx & 7;
        g_h[b * 1024 + j0 + jj] = __float2half_rn(0.0f);
    }
    float cst[8];
    #pragma unroll
    for (int i = 0; i < 8; ++i) cst[i] = 0.0f;

    int srow[8], sc4[8];
    #pragma unroll
    for (int it = 0; it < 8; ++it) {
        int idx = tid + 256 * it;
        srow[it] = idx >> 4;
        sc4[it]  = (idx & 15) * 4;
    }

    grid_barrier();

    for (int t = 0; t < 256; ++t) {
        const uint32_t* __restrict__ hin =
            reinterpret_cast<const uint32_t*>(&g_h[(t & 1) * (128 * 1024)]);
        __half* __restrict__ hout = &g_h[((t + 1) & 1) * (128 * 1024)];

        float acc[2][4][4];
        #pragma unroll
        for (int mt = 0; mt < 2; ++mt)
            #pragma unroll
            for (int nt = 0; nt < 4; ++nt)
                #pragma unroll
                for (int r = 0; r < 4; ++r) acc[mt][nt][r] = 0.0f;

        // prologue: stage chunks 0 and 1 into bufs 0 and 1
        #pragma unroll
        for (int pc = 0; pc < 2; ++pc) {
            uint32_t boff = (uint32_t)(pc * 128 * AS2_STRIDE) << 2;
            #pragma unroll
            for (int it = 0; it < 8; ++it) {
                uint32_t dsm = as_base + boff + ((srow[it] * AS2_STRIDE + sc4[it]) << 2);
                const uint32_t* src = hin + srow[it] * 512 + pc * 64 + sc4[it];
                asm volatile("cp.async.cg.shared.global [%0], [%1], 16;" :: "r"(dsm), "l"(src));
            }
            asm volatile("cp.async.commit_group;");
        }

        #pragma unroll
        for (int c = 0; c < 8; ++c) {
            if (c < 7) { asm volatile("cp.async.wait_group 1;"); }
            else       { asm volatile("cp.async.wait_group 0;"); }
            __syncthreads();   // chunk c visible; all warps past chunk c-1 reads

            if (c < 6) {       // issue chunk c+2 into buf (c+2)%3 (consumed at c-1)
                uint32_t boff = (uint32_t)(((c + 2) % 3) * 128 * AS2_STRIDE) << 2;
                #pragma unroll
                for (int it = 0; it < 8; ++it) {
                    uint32_t dsm = as_base + boff + ((srow[it] * AS2_STRIDE + sc4[it]) << 2);
                    const uint32_t* src = hin + srow[it] * 512 + (c + 2) * 64 + sc4[it];
                    asm volatile("cp.async.cg.shared.global [%0], [%1], 16;" :: "r"(dsm), "l"(src));
                }
                asm volatile("cp.async.commit_group;");
            }

            const uint32_t* Ab = Asb + (c % 3) * (128 * AS2_STRIDE);
            #pragma unroll
            for (int s = 0; s < 4; ++s) {
                const int fi = 2 * s + km;
                const int au = fi * 8 + p;
                const int bu = c * 64 + fi * 8 + p;
                uint32_t a[2][4];
                #pragma unroll
                for (int mt = 0; mt < 2; ++mt) {
                    int rb = mg * 32 + mt * 16 + q;
                    a[mt][0] = Ab[rb * AS2_STRIDE + au];
                    a[mt][1] = Ab[(rb + 8) * AS2_STRIDE + au];
                    a[mt][2] = Ab[rb * AS2_STRIDE + au + 4];
                    a[mt][3] = Ab[(rb + 8) * AS2_STRIDE + au + 4];
                }
                #pragma unroll
                for (int nt = 0; nt < 4; ++nt) {
                    uint32_t bb[2];
                    int nr = nt * 8 + q;
                    bb[0] = Ws[nr * WS2_STRIDE + bu];
                    bb[1] = Ws[nr * WS2_STRIDE + bu + 4];
                    mma_f16(acc[0][nt], a[0], bb);
                    mma_f16(acc[1][nt], a[1], bb);
                }
            }
        }
        __syncthreads();   // staging reads done before red aliases it

        if (km == 1) {
            float* w = &red[(mg * 32 + lane) * 33];
            #pragma unroll
            for (int mt = 0; mt < 2; ++mt)
                #pragma unroll
                for (int nt = 0; nt < 4; ++nt)
                    #pragma unroll
                    for (int r = 0; r < 4; ++r)
                        w[mt * 16 + nt * 4 + r] = acc[mt][nt][r];
        }
        __syncthreads();
        if (km == 0) {
            float2 xp[4][4];
            #pragma unroll
            for (int rr = 0; rr < 4; ++rr) {
                int row = mg * 32 + q + rr * 8;
                size_t base = ((size_t)(t * 128 + row)) * 4096 + j0 + 2 * p;
                #pragma unroll
                for (int g = 0; g < 4; ++g)
                    xp[rr][g] = __ldg(reinterpret_cast<const float2*>(&g_Xp[base + g * 1024]));
            }
            const float* w = &red[(mg * 32 + lane) * 33];
            #pragma unroll
            for (int mt = 0; mt < 2; ++mt)
                #pragma unroll
                for (int nt = 0; nt < 4; ++nt)
                    #pragma unroll
                    for (int r = 0; r < 4; ++r)
                        acc[mt][nt][r] += w[mt * 16 + nt * 4 + r];

            #pragma unroll
            for (int mt = 0; mt < 2; ++mt)
                #pragma unroll
                for (int r = 0; r < 4; ++r) {
                    int rr = mt * 2 + (r >> 1);
                    int row = mg * 32 + q + rr * 8;
                    int jj = 2 * p + (r & 1);
                    float xf = (r & 1) ? xp[rr][0].y : xp[rr][0].x;
                    float xi = (r & 1) ? xp[rr][1].y : xp[rr][1].x;
                    float xg = (r & 1) ? xp[rr][2].y : xp[rr][2].x;
                    float xo = (r & 1) ? xp[rr][3].y : xp[rr][3].x;
                    float fg = sigm(acc[mt][0][r] + xf);
                    float ig = sigm(acc[mt][1][r] + xi);
                    float gg = tanhf(acc[mt][2][r] + xg);
                    float og = sigm(acc[mt][3][r] + xo);
                    float cnew = cst[mt * 4 + r] * fg + ig * gg;
                    cst[mt * 4 + r] = cnew;
                    float hnew = tanhf(cnew) * og;
                    hout[row * 1024 + j0 + jj] = __float2half_rn(hnew);
                    out[(size_t)row * (256 * 1024) + t * 1024 + j0 + jj] = hnew;
                }
        }
        grid_barrier();
    }
}

// ---------------------------------------------------------------------------
extern "C" void kernel_launch(void* const* d_in, const int* in_sizes, int n_in,
                              void* d_out, int out_size) {
    const float* x  = (const float*)d_in[0];
    const float* Wf = (const float*)d_in[1];
    const float* bf = (const float*)d_in[2];
    const float* Wi = (const float*)d_in[3];
    const float* bi = (const float*)d_in[4];
    const float* Wc = (const float*)d_in[5];
    const float* bc = (const float*)d_in[6];
    const float* Wo = (const float*)d_in[7];
    const float* bo = (const float*)d_in[8];
    float* out = (float*)d_out;

    cudaFuncSetAttribute(lstm_scan_kernel,
                         cudaFuncAttributeMaxDynamicSharedMemorySize, SMEM2_BYTES);

    dim3 g1(4096 / 128, 32768 / 128);
    xproj_kernel<<<g1, 256>>>(x, Wf, bf, Wi, bi, Wc, bc, Wo, bo);
    lstm_scan_kernel<<<NBLK2, 256, SMEM2_BYTES>>>(Wf, Wi, Wc, Wo, out);
}

// round 10
// speedup vs baseline: 1.9759x; 1.0317x over previous
#include <cuda_runtime.h>
#include <cuda_fp16.h>
#include <cstdint>
#include <math.h>

// LSTM B=128, S=256, I=1024, H=1024. out[b,s,h] fp32.
// Phase 1: Xp = x @ Wx^T + bias (fp16 mma m16n8k16, fp32 accum, 128x128 tiles)
// Phase 2: persistent 128-CTA scan, fp16 h/Wh, PAIR-SCOPED triple-buffered
//          cp.async pipelines (named barriers, no block syncs in chunk loop).

#define NBLK2 128
#define WS2_STRIDE 516               // 512 + 4 pad (u32) ; row = 1024 fp16
#define AS2_STRIDE 68                // 64 + 4 pad (u32)  ; row = 128 fp16 chunk
#define PAIR_SLAB (3 * 32 * AS2_STRIDE)                 // u32 per pair (3 bufs x 32 rows)
#define RED_OFF   (32 * WS2_STRIDE + 4 * PAIR_SLAB)     // u32 offset of reduction area
#define SMEM2_BYTES ((RED_OFF + 128 * 33) * 4)          // 187,392 B

__device__ __align__(16) float    g_Xp[(size_t)256 * 128 * 4096];  // 512 MB
__device__ __align__(16) __half   g_h[2 * 128 * 1024];             // h fp16, dbl buf
__device__ unsigned g_arrive = 0;

__device__ __forceinline__ uint32_t packh2(float a, float b) {
    __half2 h = __floats2half2_rn(a, b);
    return *reinterpret_cast<uint32_t*>(&h);
}

__device__ __forceinline__ void mma_f16(float d[4], const uint32_t a[4], const uint32_t b[2]) {
    asm volatile(
        "mma.sync.aligned.m16n8k16.row.col.f32.f16.f16.f32 "
        "{%0,%1,%2,%3},{%4,%5,%6,%7},{%8,%9},{%0,%1,%2,%3};"
        : "+f"(d[0]), "+f"(d[1]), "+f"(d[2]), "+f"(d[3])
        : "r"(a[0]), "r"(a[1]), "r"(a[2]), "r"(a[3]), "r"(b[0]), "r"(b[1]));
}

__device__ __forceinline__ float sigm(float x) { return 1.0f / (1.0f + expf(-x)); }

// ---------------------------------------------------------------------------
// Phase 1: block tile 128x128, BK=32 (fp16), 8 warps (2m x 4n), warp 64x32.
// ---------------------------------------------------------------------------
__global__ __launch_bounds__(256) void xproj_kernel(
    const float* __restrict__ x,
    const float* __restrict__ Wf, const float* __restrict__ bf,
    const float* __restrict__ Wi, const float* __restrict__ bi,
    const float* __restrict__ Wc, const float* __restrict__ bc,
    const float* __restrict__ Wo, const float* __restrict__ bo)
{
    __shared__ uint32_t As[128][20];
    __shared__ uint32_t Bs[128][20];

    const float* Wsel[4] = {Wf, Wi, Wc, Wo};
    const float* bsel[4] = {bf, bi, bc, bo};

    const int tid  = threadIdx.x;
    const int warp = tid >> 5;
    const int lane = tid & 31;
    const int q = lane >> 2, p = lane & 3;
    const int wm = warp >> 2;
    const int wn = warp & 3;
    const int gate = blockIdx.x >> 3;
    const int r0 = (blockIdx.x & 7) * 128;
    const int m0 = blockIdx.y * 128;
    const float* __restrict__ Wg = Wsel[gate];
    const float* __restrict__ bg = bsel[gate];

    const int arow[4] = { tid >> 3, (tid+256) >> 3, (tid+512) >> 3, (tid+768) >> 3 };
    const int ac4 = (tid & 7) * 4;
    const int acu = (tid & 7) * 2;

    float acc[4][4][4];
    #pragma unroll
    for (int mt = 0; mt < 4; ++mt)
        #pragma unroll
        for (int nt = 0; nt < 4; ++nt)
            #pragma unroll
            for (int r = 0; r < 4; ++r) acc[mt][nt][r] = 0.0f;

    float4 ar[4], br[4];

    #pragma unroll
    for (int it = 0; it < 4; ++it) {
        ar[it] = *reinterpret_cast<const float4*>(&x[(size_t)(m0 + arow[it]) * 1024 + ac4]);
        br[it] = *reinterpret_cast<const float4*>(&Wg[(size_t)(r0 + arow[it]) * 2048 + 1024 + ac4]);
    }
    #pragma unroll
    for (int it = 0; it < 4; ++it) {
        uint32_t* wa = &As[arow[it]][acu];
        wa[0] = packh2(ar[it].x, ar[it].y); wa[1] = packh2(ar[it].z, ar[it].w);
        uint32_t* wb = &Bs[arow[it]][acu];
        wb[0] = packh2(br[it].x, br[it].y); wb[1] = packh2(br[it].z, br[it].w);
    }
    __syncthreads();

    for (int k0 = 0; k0 < 1024; k0 += 32) {
        if (k0 < 992) {
            #pragma unroll
            for (int it = 0; it < 4; ++it) {
                ar[it] = *reinterpret_cast<const float4*>(
                    &x[(size_t)(m0 + arow[it]) * 1024 + k0 + 32 + ac4]);
                br[it] = *reinterpret_cast<const float4*>(
                    &Wg[(size_t)(r0 + arow[it]) * 2048 + 1024 + k0 + 32 + ac4]);
            }
        }

        #pragma unroll
        for (int ks = 0; ks < 2; ++ks) {
            const int kk = ks * 8;
            uint32_t a[4][4];
            #pragma unroll
            for (int mt = 0; mt < 4; ++mt) {
                int rb = wm * 64 + mt * 16 + q;
                a[mt][0] = As[rb][kk + p];
                a[mt][1] = As[rb + 8][kk + p];
                a[mt][2] = As[rb][kk + p + 4];
                a[mt][3] = As[rb + 8][kk + p + 4];
            }
            #pragma unroll
            for (int nt = 0; nt < 4; ++nt) {
                uint32_t bb[2];
                int nr = wn * 32 + nt * 8 + q;
                bb[0] = Bs[nr][kk + p];
                bb[1] = Bs[nr][kk + p + 4];
                #pragma unroll
                for (int mt = 0; mt < 4; ++mt)
                    mma_f16(acc[mt][nt], a[mt], bb);
            }
        }
        __syncthreads();
        if (k0 < 992) {
            #pragma unroll
            for (int it = 0; it < 4; ++it) {
                uint32_t* wa = &As[arow[it]][acu];
                wa[0] = packh2(ar[it].x, ar[it].y); wa[1] = packh2(ar[it].z, ar[it].w);
                uint32_t* wb = &Bs[arow[it]][acu];
                wb[0] = packh2(br[it].x, br[it].y); wb[1] = packh2(br[it].z, br[it].w);
            }
            __syncthreads();
        }
    }

    #pragma unroll
    for (int mt = 0; mt < 4; ++mt)
        #pragma unroll
        for (int nt = 0; nt < 4; ++nt)
            #pragma unroll
            for (int r = 0; r < 4; ++r) {
                int row = wm * 64 + mt * 16 + q + ((r >> 1) << 3);
                int col = wn * 32 + nt * 8 + 2 * p + (r & 1);
                int m = m0 + row;
                int b = m >> 8;
                int s = m & 255;
                g_Xp[((size_t)(s * 128 + b) * 4096) + gate * 1024 + r0 + col] =
                    acc[mt][nt][r] + bg[r0 + col];
            }
}

// ---------------------------------------------------------------------------
// Phase 2: 256 threads, 8 warps = 4 pairs {mg, mg+4}. Each pair owns a private
// triple-buffered slab and pipelines its 32-batch slice independently.
// ---------------------------------------------------------------------------
__device__ __forceinline__ void grid_barrier() {
    __threadfence();
    __syncthreads();
    if (threadIdx.x == 0) {
        unsigned old = atomicAdd(&g_arrive, 1u);
        unsigned target = (old / gridDim.x + 1u) * gridDim.x;
        while (*(volatile unsigned*)&g_arrive < target) {
            __nanosleep(32);
        }
        __threadfence();
    }
    __syncthreads();
}

__global__ void __launch_bounds__(256, 1) lstm_scan_kernel(
    const float* __restrict__ Wf, const float* __restrict__ Wi,
    const float* __restrict__ Wc, const float* __restrict__ Wo,
    float* __restrict__ out)
{
    extern __shared__ uint8_t smem[];
    uint32_t* Ws  = reinterpret_cast<uint32_t*>(smem);                 // [32][WS2_STRIDE]
    uint32_t* Stg = reinterpret_cast<uint32_t*>(smem) + 32 * WS2_STRIDE; // [4][3][32][AS2_STRIDE]
    float*    red = reinterpret_cast<float*>(smem) + RED_OFF;          // [128][33]

    const float* Wsel[4] = {Wf, Wi, Wc, Wo};
    const int tid  = threadIdx.x;
    const int warp = tid >> 5;
    const int lane = tid & 31;
    const int q = lane >> 2, p = lane & 3;
    const int mg = warp & 3;     // pair id (32 batches)
    const int km = warp >> 2;    // member in pair (k-interleave)
    const int j0 = blockIdx.x * 8;

    uint32_t* slab = Stg + mg * PAIR_SLAB;
    const uint32_t slab_base = (uint32_t)__cvta_generic_to_shared(slab);

    // Load Wh slice as fp16 pairs
    for (int idx = tid; idx < 32 * 256; idx += 256) {
        int cc = idx >> 8;
        int k4 = (idx & 255) * 4;
        int g = cc >> 3, jj = cc & 7;
        const float* Wg = Wsel[g];
        float4 v = *reinterpret_cast<const float4*>(&Wg[(size_t)(j0 + jj) * 2048 + k4]);
        uint32_t* wr = &Ws[cc * WS2_STRIDE + (k4 >> 1)];
        wr[0] = packh2(v.x, v.y);
        wr[1] = packh2(v.z, v.w);
    }
    for (int idx = tid; idx < 1024; idx += 256) {
        int b = idx >> 3, jj = idx & 7;
        g_h[b * 1024 + j0 + jj] = __float2half_rn(0.0f);
    }
    float cst[8];
    #pragma unroll
    for (int i = 0; i < 8; ++i) cst[i] = 0.0f;

    // pair-local staging mapping: 64 threads stage 32 rows x 64 u32 per chunk
    const int tid64 = km * 32 + lane;       // 0..63 within pair
    int srow[8], sc4[8];
    #pragma unroll
    for (int it = 0; it < 8; ++it) {
        int idx = tid64 + 64 * it;          // 0..511
        srow[it] = idx >> 4;                // 0..31 (local row)
        sc4[it]  = (idx & 15) * 4;          // u32 col in chunk (0..60)
    }

    grid_barrier();

    for (int t = 0; t < 256; ++t) {
        const uint32_t* __restrict__ hin =
            reinterpret_cast<const uint32_t*>(&g_h[(t & 1) * (128 * 1024)]);
        __half* __restrict__ hout = &g_h[((t + 1) & 1) * (128 * 1024)];
        // pair reads rows mg*32..+31 only
        const uint32_t* __restrict__ hrow0 = hin + (size_t)(mg * 32) * 512;

        // prefetch Xp for this step (km==0 epilogue owners) — hidden under chunk loop
        float2 xp[4][4];
        if (km == 0) {
            #pragma unroll
            for (int rr = 0; rr < 4; ++rr) {
                int row = mg * 32 + q + rr * 8;
                size_t base = ((size_t)(t * 128 + row)) * 4096 + j0 + 2 * p;
                #pragma unroll
                for (int g = 0; g < 4; ++g)
                    xp[rr][g] = __ldg(reinterpret_cast<const float2*>(&g_Xp[base + g * 1024]));
            }
        }

        float acc[2][4][4];
        #pragma unroll
        for (int mt = 0; mt < 2; ++mt)
            #pragma unroll
            for (int nt = 0; nt < 4; ++nt)
                #pragma unroll
                for (int r = 0; r < 4; ++r) acc[mt][nt][r] = 0.0f;

        // prologue: stage chunks 0,1 into bufs 0,1 (pair-private)
        #pragma unroll
        for (int pc = 0; pc < 2; ++pc) {
            uint32_t boff = (uint32_t)(pc * 32 * AS2_STRIDE) << 2;
            #pragma unroll
            for (int it = 0; it < 8; ++it) {
                uint32_t dsm = slab_base + boff + ((srow[it] * AS2_STRIDE + sc4[it]) << 2);
                const uint32_t* src = hrow0 + srow[it] * 512 + pc * 64 + sc4[it];
                asm volatile("cp.async.cg.shared.global [%0], [%1], 16;" :: "r"(dsm), "l"(src));
            }
            asm volatile("cp.async.commit_group;");
        }

        #pragma unroll
        for (int c = 0; c < 8; ++c) {
            if (c < 7) { asm volatile("cp.async.wait_group 1;"); }
            else       { asm volatile("cp.async.wait_group 0;"); }
            asm volatile("bar.sync %0, 64;" :: "r"(1 + mg) : "memory");  // pair barrier

            if (c < 6) {   // issue chunk c+2 into buf (c+2)%3 (pair done with c-1)
                uint32_t boff = (uint32_t)(((c + 2) % 3) * 32 * AS2_STRIDE) << 2;
                #pragma unroll
                for (int it = 0; it < 8; ++it) {
                    uint32_t dsm = slab_base + boff + ((srow[it] * AS2_STRIDE + sc4[it]) << 2);
                    const uint32_t* src = hrow0 + srow[it] * 512 + (c + 2) * 64 + sc4[it];
                    asm volatile("cp.async.cg.shared.global [%0], [%1], 16;" :: "r"(dsm), "l"(src));
                }
                asm volatile("cp.async.commit_group;");
            }

            const uint32_t* Ab = slab + (c % 3) * (32 * AS2_STRIDE);
            #pragma unroll
            for (int s = 0; s < 4; ++s) {
                const int fi = 2 * s + km;              // k16 frag in chunk (0..7)
                const int au = fi * 8 + p;
                const int bu = c * 64 + fi * 8 + p;     // u32 col in Ws row
                uint32_t a[2][4];
                #pragma unroll
                for (int mt = 0; mt < 2; ++mt) {
                    int rb = mt * 16 + q;               // local row in pair slab
                    a[mt][0] = Ab[rb * AS2_STRIDE + au];
                    a[mt][1] = Ab[(rb + 8) * AS2_STRIDE + au];
                    a[mt][2] = Ab[rb * AS2_STRIDE + au + 4];
                    a[mt][3] = Ab[(rb + 8) * AS2_STRIDE + au + 4];
                }
                #pragma unroll
                for (int nt = 0; nt < 4; ++nt) {
                    uint32_t bb[2];
                    int nr = nt * 8 + q;
                    bb[0] = Ws[nr * WS2_STRIDE + bu];
                    bb[1] = Ws[nr * WS2_STRIDE + bu + 4];
                    mma_f16(acc[0][nt], a[0], bb);
                    mma_f16(acc[1][nt], a[1], bb);
                }
            }
        }

        // 2-way k reduction through dedicated smem (no aliasing with staging)
        if (km == 1) {
            float* w = &red[(mg * 32 + lane) * 33];
            #pragma unroll
            for (int mt = 0; mt < 2; ++mt)
                #pragma unroll
                for (int nt = 0; nt < 4; ++nt)
                    #pragma unroll
                    for (int r = 0; r < 4; ++r)
                        w[mt * 16 + nt * 4 + r] = acc[mt][nt][r];
        }
        asm volatile("bar.sync %0, 64;" :: "r"(1 + mg) : "memory");  // pair hand-off
        if (km == 0) {
            const float* w = &red[(mg * 32 + lane) * 33];
            #pragma unroll
            for (int mt = 0; mt < 2; ++mt)
                #pragma unroll
                for (int nt = 0; nt < 4; ++nt)
                    #pragma unroll
                    for (int r = 0; r < 4; ++r)
                        acc[mt][nt][r] += w[mt * 16 + nt * 4 + r];

            #pragma unroll
            for (int mt = 0; mt < 2; ++mt)
                #pragma unroll
                for (int r = 0; r < 4; ++r) {
                    int rr = mt * 2 + (r >> 1);
                    int row = mg * 32 + q + rr * 8;
                    int jj = 2 * p + (r & 1);
                    float xf = (r & 1) ? xp[rr][0].y : xp[rr][0].x;
                    float xi = (r & 1) ? xp[rr][1].y : xp[rr][1].x;
                    float xg = (r & 1) ? xp[rr][2].y : xp[rr][2].x;
                    float xo = (r & 1) ? xp[rr][3].y : xp[rr][3].x;
                    float fg = sigm(acc[mt][0][r] + xf);
                    float ig = sigm(acc[mt][1][r] + xi);
                    float gg = tanhf(acc[mt][2][r] + xg);
                    float og = sigm(acc[mt][3][r] + xo);
                    float cnew = cst[mt * 4 + r] * fg + ig * gg;
                    cst[mt * 4 + r] = cnew;
                    float hnew = tanhf(cnew) * og;
                    hout[row * 1024 + j0 + jj] = __float2half_rn(hnew);
                    out[(size_t)row * (256 * 1024) + t * 1024 + j0 + jj] = hnew;
                }
        }
        grid_barrier();
    }
}

// ---------------------------------------------------------------------------
extern "C" void kernel_launch(void* const* d_in, const int* in_sizes, int n_in,
                              void* d_out, int out_size) {
    const float* x  = (const float*)d_in[0];
    const float* Wf = (const float*)d_in[1];
    const float* bf = (const float*)d_in[2];
    const float* Wi = (const float*)d_in[3];
    const float* bi = (const float*)d_in[4];
    const float* Wc = (const float*)d_in[5];
    const float* bc = (const float*)d_in[6];
    const float* Wo = (const float*)d_in[7];
    const float* bo = (const float*)d_in[8];
    float* out = (float*)d_out;

    cudaFuncSetAttribute(lstm_scan_kernel,
                         cudaFuncAttributeMaxDynamicSharedMemorySize, SMEM2_BYTES);

    dim3 g1(4096 / 128, 32768 / 128);
    xproj_kernel<<<g1, 256>>>(x, Wf, bf, Wi, bi, Wc, bc, Wo, bo);
    lstm_scan_kernel<<<NBLK2, 256, SMEM2_BYTES>>>(Wf, Wi, Wc, Wo, out);
}